// round 1
// baseline (speedup 1.0000x reference)
#include <cuda_runtime.h>

// Problem constants
#define BB 4
#define SS 2048
#define FF 1024

// Scratch (static device globals — no allocation)
__device__ float g_qp[BB * SS * FF];            // 32 MB
__device__ float g_kp[BB * SS * FF];            // 32 MB
__device__ float g_vp[BB * SS * FF];            // 32 MB
__device__ float g_attn[BB * SS * SS];          // 64 MB

// ---------------------------------------------------------------------------
// SGEMM NT:  C[m,n] = sum_k A[m,k] * B[n,k]  (+ bias[n] if bias != null)
// A: [M,K] row-major, B: [N,K] row-major, C: [M,N] row-major. Batched via z.
// BM=BN=128, BK=16, 256 threads, 8x8 per thread. Dims must divide tiles.
// ---------------------------------------------------------------------------
__global__ __launch_bounds__(256) void gemm_nt_kernel(
    const float* __restrict__ A, const float* __restrict__ B,
    const float* __restrict__ bias, float* __restrict__ C,
    int M, int N, int K,
    long long sA, long long sB, long long sC)
{
    constexpr int BM = 128, BN = 128, BK = 16;
    __shared__ float As[BK][BM];
    __shared__ float Bs[BK][BN];

    const float* Ab = A + (long long)blockIdx.z * sA;
    const float* Bb = B + (long long)blockIdx.z * sB;
    float*       Cb = C + (long long)blockIdx.z * sC;

    const int tid  = threadIdx.x;
    const int row0 = blockIdx.y * BM;
    const int col0 = blockIdx.x * BN;
    const int tr   = tid >> 4;   // 0..15
    const int tc   = tid & 15;   // 0..15

    float acc[8][8];
#pragma unroll
    for (int i = 0; i < 8; i++)
#pragma unroll
        for (int j = 0; j < 8; j++) acc[i][j] = 0.f;

    for (int k0 = 0; k0 < K; k0 += BK) {
        // 128 rows x 16 k-cols per tile = 512 float4; 2 per thread for A and B
#pragma unroll
        for (int l = 0; l < 2; l++) {
            int idx = tid + l * 256;
            int r   = idx >> 2;   // 0..127
            int c4  = idx & 3;    // 0..3
            float4 va = *reinterpret_cast<const float4*>(
                &Ab[(long long)(row0 + r) * K + k0 + c4 * 4]);
            As[c4 * 4 + 0][r] = va.x;
            As[c4 * 4 + 1][r] = va.y;
            As[c4 * 4 + 2][r] = va.z;
            As[c4 * 4 + 3][r] = va.w;
            float4 vb = *reinterpret_cast<const float4*>(
                &Bb[(long long)(col0 + r) * K + k0 + c4 * 4]);
            Bs[c4 * 4 + 0][r] = vb.x;
            Bs[c4 * 4 + 1][r] = vb.y;
            Bs[c4 * 4 + 2][r] = vb.z;
            Bs[c4 * 4 + 3][r] = vb.w;
        }
        __syncthreads();

#pragma unroll
        for (int k = 0; k < BK; k++) {
            float a[8], b[8];
#pragma unroll
            for (int i = 0; i < 8; i++) a[i] = As[k][tr * 8 + i];
#pragma unroll
            for (int j = 0; j < 8; j++) b[j] = Bs[k][tc * 8 + j];
#pragma unroll
            for (int i = 0; i < 8; i++)
#pragma unroll
                for (int j = 0; j < 8; j++)
                    acc[i][j] += a[i] * b[j];
        }
        __syncthreads();
    }

#pragma unroll
    for (int i = 0; i < 8; i++) {
        int r = row0 + tr * 8 + i;
#pragma unroll
        for (int j = 0; j < 8; j += 4) {
            int c = col0 + tc * 8 + j;
            float4 o;
            o.x = acc[i][j + 0];
            o.y = acc[i][j + 1];
            o.z = acc[i][j + 2];
            o.w = acc[i][j + 3];
            if (bias) {
                o.x += bias[c + 0];
                o.y += bias[c + 1];
                o.z += bias[c + 2];
                o.w += bias[c + 3];
            }
            *reinterpret_cast<float4*>(&Cb[(long long)r * N + c]) = o;
        }
    }
}

// ---------------------------------------------------------------------------
// SGEMM NN + residual:  C[m,n] = sum_k A[m,k]*B[k,n] + R[m,n]
// A: [M,K] row-major, B: [K,N] row-major. Batched via z (R,C share stride sR).
// ---------------------------------------------------------------------------
__global__ __launch_bounds__(256) void gemm_nn_res_kernel(
    const float* __restrict__ A, const float* __restrict__ B,
    const float* __restrict__ R, float* __restrict__ C,
    int M, int N, int K,
    long long sA, long long sB, long long sR)
{
    constexpr int BM = 128, BN = 128, BK = 16;
    __shared__ float As[BK][BM];
    __shared__ float Bs[BK][BN];

    const float* Ab = A + (long long)blockIdx.z * sA;
    const float* Bb = B + (long long)blockIdx.z * sB;
    const float* Rb = R + (long long)blockIdx.z * sR;
    float*       Cb = C + (long long)blockIdx.z * sR;

    const int tid  = threadIdx.x;
    const int row0 = blockIdx.y * BM;
    const int col0 = blockIdx.x * BN;
    const int tr   = tid >> 4;
    const int tc   = tid & 15;

    float acc[8][8];
#pragma unroll
    for (int i = 0; i < 8; i++)
#pragma unroll
        for (int j = 0; j < 8; j++) acc[i][j] = 0.f;

    for (int k0 = 0; k0 < K; k0 += BK) {
        // A tile: transpose-store (same as NT)
#pragma unroll
        for (int l = 0; l < 2; l++) {
            int idx = tid + l * 256;
            int r   = idx >> 2;
            int c4  = idx & 3;
            float4 va = *reinterpret_cast<const float4*>(
                &Ab[(long long)(row0 + r) * K + k0 + c4 * 4]);
            As[c4 * 4 + 0][r] = va.x;
            As[c4 * 4 + 1][r] = va.y;
            As[c4 * 4 + 2][r] = va.z;
            As[c4 * 4 + 3][r] = va.w;
            // B tile: [BK x BN] natural layout, float4 along n
            int kr  = idx >> 5;   // 0..15
            int cc4 = idx & 31;   // 0..31
            float4 vb = *reinterpret_cast<const float4*>(
                &Bb[(long long)(k0 + kr) * N + col0 + cc4 * 4]);
            *reinterpret_cast<float4*>(&Bs[kr][cc4 * 4]) = vb;
        }
        __syncthreads();

#pragma unroll
        for (int k = 0; k < BK; k++) {
            float a[8], b[8];
#pragma unroll
            for (int i = 0; i < 8; i++) a[i] = As[k][tr * 8 + i];
#pragma unroll
            for (int j = 0; j < 8; j++) b[j] = Bs[k][tc * 8 + j];
#pragma unroll
            for (int i = 0; i < 8; i++)
#pragma unroll
                for (int j = 0; j < 8; j++)
                    acc[i][j] += a[i] * b[j];
        }
        __syncthreads();
    }

#pragma unroll
    for (int i = 0; i < 8; i++) {
        int r = row0 + tr * 8 + i;
#pragma unroll
        for (int j = 0; j < 8; j += 4) {
            int c = col0 + tc * 8 + j;
            float4 res = *reinterpret_cast<const float4*>(&Rb[(long long)r * N + c]);
            float4 o;
            o.x = acc[i][j + 0] + res.x;
            o.y = acc[i][j + 1] + res.y;
            o.z = acc[i][j + 2] + res.z;
            o.w = acc[i][j + 3] + res.w;
            *reinterpret_cast<float4*>(&Cb[(long long)r * N + c]) = o;
        }
    }
}

// ---------------------------------------------------------------------------
// Row softmax, in place. One CTA per row of length SS=2048, 256 threads.
// Max-subtraction is mandatory: unscaled logits reach ~±110.
// ---------------------------------------------------------------------------
__global__ __launch_bounds__(256) void softmax_kernel(float* __restrict__ attn)
{
    __shared__ float red[8];
    const long long row = blockIdx.x;
    float* p = attn + row * (long long)SS;
    const int tid = threadIdx.x;

    float vals[8];
    float lmax = -1e30f;
#pragma unroll
    for (int i = 0; i < 8; i++) {
        vals[i] = p[tid + i * 256];
        lmax = fmaxf(lmax, vals[i]);
    }
#pragma unroll
    for (int o = 16; o > 0; o >>= 1)
        lmax = fmaxf(lmax, __shfl_xor_sync(0xffffffffu, lmax, o));
    if ((tid & 31) == 0) red[tid >> 5] = lmax;
    __syncthreads();
    float bmax = red[0];
#pragma unroll
    for (int w = 1; w < 8; w++) bmax = fmaxf(bmax, red[w]);
    __syncthreads();

    float lsum = 0.f;
#pragma unroll
    for (int i = 0; i < 8; i++) {
        vals[i] = expf(vals[i] - bmax);
        lsum += vals[i];
    }
#pragma unroll
    for (int o = 16; o > 0; o >>= 1)
        lsum += __shfl_xor_sync(0xffffffffu, lsum, o);
    if ((tid & 31) == 0) red[tid >> 5] = lsum;
    __syncthreads();
    float total = 0.f;
#pragma unroll
    for (int w = 0; w < 8; w++) total += red[w];
    float inv = 1.0f / total;

#pragma unroll
    for (int i = 0; i < 8; i++)
        p[tid + i * 256] = vals[i] * inv;
}

// ---------------------------------------------------------------------------
// Launch: 3 projections (NT+bias) -> logits (batched NT) -> softmax ->
//         attn@vp + q (batched NN + residual)
// ---------------------------------------------------------------------------
extern "C" void kernel_launch(void* const* d_in, const int* in_sizes, int n_in,
                              void* d_out, int out_size)
{
    (void)in_sizes; (void)n_in; (void)out_size;
    const float* q  = (const float*)d_in[0];
    const float* k  = (const float*)d_in[1];
    const float* v  = (const float*)d_in[2];
    const float* Wq = (const float*)d_in[3];
    const float* bq = (const float*)d_in[4];
    const float* Wk = (const float*)d_in[5];
    const float* bk = (const float*)d_in[6];
    const float* Wv = (const float*)d_in[7];
    const float* bv = (const float*)d_in[8];
    float* out = (float*)d_out;

    float *qp, *kp, *vp, *attn;
    cudaGetSymbolAddress((void**)&qp,   g_qp);
    cudaGetSymbolAddress((void**)&kp,   g_kp);
    cudaGetSymbolAddress((void**)&vp,   g_vp);
    cudaGetSymbolAddress((void**)&attn, g_attn);

    dim3 blk(256);

    // Projections: M = B*S = 8192, N = K = F = 1024
    dim3 gproj(FF / 128, (BB * SS) / 128, 1);
    gemm_nt_kernel<<<gproj, blk>>>(q, Wq, bq, qp, BB * SS, FF, FF, 0, 0, 0);
    gemm_nt_kernel<<<gproj, blk>>>(k, Wk, bk, kp, BB * SS, FF, FF, 0, 0, 0);
    gemm_nt_kernel<<<gproj, blk>>>(v, Wv, bv, vp, BB * SS, FF, FF, 0, 0, 0);

    // Logits: per batch 2048x2048 over K=1024
    dim3 glog(SS / 128, SS / 128, BB);
    gemm_nt_kernel<<<glog, blk>>>(qp, kp, nullptr, attn, SS, SS, FF,
                                  (long long)SS * FF, (long long)SS * FF,
                                  (long long)SS * SS);

    // Softmax over rows of length SS
    softmax_kernel<<<BB * SS, 256>>>(attn);

    // Output: attn @ vp + q, per batch 2048x1024 over K=2048
    dim3 gout(FF / 128, SS / 128, BB);
    gemm_nn_res_kernel<<<gout, blk>>>(attn, vp, q, out, SS, FF, SS,
                                      (long long)SS * SS, (long long)SS * FF,
                                      (long long)SS * FF);
}

// round 3
// speedup vs baseline: 2.8815x; 2.8815x over previous
#include <cuda_runtime.h>
#include <cuda_bf16.h>
#include <cstdint>

#define BB 4
#define SS 2048
#define FF 1024
#define BS (BB*SS)

// ---------------------------------------------------------------------------
// Scratch (static device globals — no allocation)
// ---------------------------------------------------------------------------
__device__ __align__(16) __nv_bfloat16 g_qh[BS*FF],  g_ql[BS*FF];
__device__ __align__(16) __nv_bfloat16 g_kh[BS*FF],  g_kl[BS*FF];
__device__ __align__(16) __nv_bfloat16 g_vh[BS*FF],  g_vl[BS*FF];
__device__ __align__(16) __nv_bfloat16 g_wqh[FF*FF], g_wql[FF*FF];
__device__ __align__(16) __nv_bfloat16 g_wkh[FF*FF], g_wkl[FF*FF];
__device__ __align__(16) __nv_bfloat16 g_wvh[FF*FF], g_wvl[FF*FF];
__device__ __align__(16) __nv_bfloat16 g_qph[BS*FF], g_qpl[BS*FF];
__device__ __align__(16) __nv_bfloat16 g_kph[BS*FF], g_kpl[BS*FF];
__device__ __align__(16) __nv_bfloat16 g_vpth[BS*FF], g_vptl[BS*FF];   // vp^T [b][f][s]
__device__ float g_attn[BB*SS*SS];                                      // fp32 logits
__device__ __align__(16) __nv_bfloat16 g_ath[BB*SS*SS], g_atl[BB*SS*SS];

// ---------------------------------------------------------------------------
// PTX helpers (compute_103-safe: cp.async / ldmatrix / mma.sync only)
// ---------------------------------------------------------------------------
__device__ __forceinline__ uint32_t smem_u32(const void* p) {
    uint32_t a;
    asm("{ .reg .u64 t; cvta.to.shared.u64 t, %1; cvt.u32.u64 %0, t; }"
        : "=r"(a) : "l"(p));
    return a;
}

#define CP_ASYNC16(dst, src)                                                  \
    asm volatile("cp.async.cg.shared.global [%0], [%1], 16;"                  \
                 :: "r"(dst), "l"(src))
#define CP_COMMIT() asm volatile("cp.async.commit_group;" ::: "memory")
#define CP_WAIT(n)  asm volatile("cp.async.wait_group %0;" :: "n"(n) : "memory")

#define LDSM4(R, addr)                                                        \
    asm volatile("ldmatrix.sync.aligned.m8n8.x4.shared.b16 {%0,%1,%2,%3}, [%4];" \
                 : "=r"((R)[0]), "=r"((R)[1]), "=r"((R)[2]), "=r"((R)[3])     \
                 : "r"(addr))

#define MMA(D, A, B0, B1)                                                     \
    asm volatile("mma.sync.aligned.m16n8k16.row.col.f32.bf16.bf16.f32 "       \
                 "{%0,%1,%2,%3}, {%4,%5,%6,%7}, {%8,%9}, {%0,%1,%2,%3};"      \
                 : "+f"((D)[0]), "+f"((D)[1]), "+f"((D)[2]), "+f"((D)[3])     \
                 : "r"((A)[0]), "r"((A)[1]), "r"((A)[2]), "r"((A)[3]),        \
                   "r"(B0), "r"(B1))

// ---------------------------------------------------------------------------
// fp32 -> bf16 hi/lo split
// ---------------------------------------------------------------------------
__global__ __launch_bounds__(256) void split_kernel(
    const float* __restrict__ src,
    __nv_bfloat16* __restrict__ hi, __nv_bfloat16* __restrict__ lo, int n4)
{
    int i = blockIdx.x * 256 + threadIdx.x;
    if (i >= n4) return;
    float4 v = reinterpret_cast<const float4*>(src)[i];
    __nv_bfloat16 h0 = __float2bfloat16(v.x);
    __nv_bfloat16 h1 = __float2bfloat16(v.y);
    __nv_bfloat16 h2 = __float2bfloat16(v.z);
    __nv_bfloat16 h3 = __float2bfloat16(v.w);
    __nv_bfloat16 l0 = __float2bfloat16(v.x - __bfloat162float(h0));
    __nv_bfloat16 l1 = __float2bfloat16(v.y - __bfloat162float(h1));
    __nv_bfloat16 l2 = __float2bfloat16(v.z - __bfloat162float(h2));
    __nv_bfloat16 l3 = __float2bfloat16(v.w - __bfloat162float(h3));
    __nv_bfloat162* H = reinterpret_cast<__nv_bfloat162*>(hi);
    __nv_bfloat162* L = reinterpret_cast<__nv_bfloat162*>(lo);
    H[2*i]   = __halves2bfloat162(h0, h1);
    H[2*i+1] = __halves2bfloat162(h2, h3);
    L[2*i]   = __halves2bfloat162(l0, l1);
    L[2*i+1] = __halves2bfloat162(l2, l3);
}

// ---------------------------------------------------------------------------
// mma.sync split-bf16 GEMM (NT): C[m,n] = sum_k A[m,k]*B[n,k]
//   = Ah*Bh + Ah*Bl + Al*Bh   (fp32 accum in registers)
// CTA tile 128x128, BK=32, 8 warps (4 M x 2 N), warp tile 32x64.
// Double-buffered cp.async smem; padded rows (40 elems) -> conflict-free ldmatrix.
// mode 0: outF = acc (+ residual)
// mode 1: acc + bias -> hi/lo bf16 at [m*ldc + n]
// mode 2: acc + bias -> hi/lo bf16 transposed [(b*FF+n)*SS + s], m=b*SS+s
// ---------------------------------------------------------------------------
#define PADW   40                 // padded row length in bf16 elems (80 B)
#define TILEB  (128*PADW*2)       // 10240 B per tile
#define OFF_AH 0
#define OFF_AL (1*TILEB)
#define OFF_BH (2*TILEB)
#define OFF_BL (3*TILEB)
#define STAGEB (4*TILEB)          // 40960
#define SMEMB  (2*STAGEB)         // 81920

__device__ __forceinline__ void load_stage(
    uint32_t sdst,
    const __nv_bfloat16* pAh, const __nv_bfloat16* pAl,
    const __nv_bfloat16* pBh, const __nv_bfloat16* pBl,
    int row0, int col0, int K, int k0, int tid)
{
    const int ch = tid & 3;
    const int rb = tid >> 2;            // 0..63
#pragma unroll
    for (int t = 0; t < 8; ++t) {
        const int tile = t >> 1;        // compile-time under unroll
        const int r = rb + (t & 1) * 64;
        uint32_t sm = sdst + tile * TILEB + r * (PADW*2) + ch * 16;
        const __nv_bfloat16* g;
        if (tile == 0)      g = pAh + (long long)(row0 + r) * K + k0 + ch * 8;
        else if (tile == 1) g = pAl + (long long)(row0 + r) * K + k0 + ch * 8;
        else if (tile == 2) g = pBh + (long long)(col0 + r) * K + k0 + ch * 8;
        else                g = pBl + (long long)(col0 + r) * K + k0 + ch * 8;
        CP_ASYNC16(sm, g);
    }
}

__global__ __launch_bounds__(256, 2) void gemm_mma_kernel(
    const __nv_bfloat16* __restrict__ Ah, const __nv_bfloat16* __restrict__ Al,
    const __nv_bfloat16* __restrict__ Bh, const __nv_bfloat16* __restrict__ Bl,
    int K, long long sA, long long sB,
    const float* __restrict__ bias,
    const float* __restrict__ residual, long long sR,
    float* __restrict__ outF, long long sC, int ldc,
    __nv_bfloat16* __restrict__ outH, __nv_bfloat16* __restrict__ outL,
    int mode)
{
    extern __shared__ char smem[];
    const uint32_t sbase = smem_u32(smem);
    const int tid = threadIdx.x;
    const int wid = tid >> 5, lid = tid & 31;
    const int warp_m = wid & 3, warp_n = wid >> 2;
    const int row0 = blockIdx.y * 128, col0 = blockIdx.x * 128;
    const long long z = blockIdx.z;

    const __nv_bfloat16* pAh = Ah + z * sA;
    const __nv_bfloat16* pAl = Al + z * sA;
    const __nv_bfloat16* pBh = Bh + z * sB;
    const __nv_bfloat16* pBl = Bl + z * sB;

    float acc[2][8][4];
#pragma unroll
    for (int t = 0; t < 2; ++t)
#pragma unroll
        for (int n = 0; n < 8; ++n)
#pragma unroll
            for (int c = 0; c < 4; ++c) acc[t][n][c] = 0.f;

    // ldmatrix per-lane address components (byte offsets within a tile)
    // A (x4: rows m0-15 x k0-15): lane -> row (lid%16), k-chunk (lid/16)*8
    const uint32_t a_part =
        ((warp_m * 32 + (lid & 15)) * PADW + ((lid >> 4) * 8)) * 2;
    // B (x4: rows n0-15 x k0-15): lanes0-7 n0-7/k0, 8-15 n0-7/k8,
    //                             16-23 n8-15/k0, 24-31 n8-15/k8
    const uint32_t b_part =
        ((warp_n * 64 + ((lid >> 4) << 3) + (lid & 7)) * PADW +
         (((lid >> 3) & 1) * 8)) * 2;

    const int iters = K >> 5;
    load_stage(sbase, pAh, pAl, pBh, pBl, row0, col0, K, 0, tid);
    CP_COMMIT();

    for (int it = 0; it < iters; ++it) {
        const uint32_t buf = (it & 1) ? (sbase + STAGEB) : sbase;
        if (it + 1 < iters) {
            const uint32_t nbuf = (it & 1) ? sbase : (sbase + STAGEB);
            load_stage(nbuf, pAh, pAl, pBh, pBl, row0, col0, K,
                       (it + 1) << 5, tid);
            CP_COMMIT();
            CP_WAIT(1);
        } else {
            CP_WAIT(0);
        }
        __syncthreads();

#pragma unroll
        for (int kk = 0; kk < 2; ++kk) {
            uint32_t a_h[2][4], a_l[2][4];
#pragma unroll
            for (int t = 0; t < 2; ++t) {
                LDSM4(a_h[t], buf + OFF_AH + a_part + (t * 16 * PADW + kk * 16) * 2);
                LDSM4(a_l[t], buf + OFF_AL + a_part + (t * 16 * PADW + kk * 16) * 2);
            }
#pragma unroll
            for (int p = 0; p < 4; ++p) {
                uint32_t b_h[4], b_l[4];
                LDSM4(b_h, buf + OFF_BH + b_part + (p * 16 * PADW + kk * 16) * 2);
                LDSM4(b_l, buf + OFF_BL + b_part + (p * 16 * PADW + kk * 16) * 2);
#pragma unroll
                for (int t = 0; t < 2; ++t) {
                    MMA(acc[t][2*p],   a_h[t], b_h[0], b_h[1]);
                    MMA(acc[t][2*p+1], a_h[t], b_h[2], b_h[3]);
                    MMA(acc[t][2*p],   a_h[t], b_l[0], b_l[1]);
                    MMA(acc[t][2*p+1], a_h[t], b_l[2], b_l[3]);
                    MMA(acc[t][2*p],   a_l[t], b_h[0], b_h[1]);
                    MMA(acc[t][2*p+1], a_l[t], b_h[2], b_h[3]);
                }
            }
        }
        __syncthreads();
    }

    // -------------------- epilogue --------------------
    const int l4 = lid >> 2;
    const int l2 = (lid & 3) * 2;
#pragma unroll
    for (int t = 0; t < 2; ++t) {
#pragma unroll
        for (int nt = 0; nt < 8; ++nt) {
#pragma unroll
            for (int h = 0; h < 2; ++h) {
                const long long R = row0 + warp_m * 32 + t * 16 + l4 + h * 8;
                const int C = col0 + warp_n * 64 + nt * 8 + l2;
                float v0 = acc[t][nt][h * 2 + 0];
                float v1 = acc[t][nt][h * 2 + 1];
                if (mode == 0) {
                    if (residual) {
                        const float* Ro = residual + z * sR + R * ldc + C;
                        v0 += Ro[0];
                        v1 += Ro[1];
                    }
                    float2 o = make_float2(v0, v1);
                    *reinterpret_cast<float2*>(outF + z * sC + R * ldc + C) = o;
                } else if (mode == 1) {
                    v0 += bias[C];
                    v1 += bias[C + 1];
                    __nv_bfloat16 h0 = __float2bfloat16(v0);
                    __nv_bfloat16 h1 = __float2bfloat16(v1);
                    __nv_bfloat16 l0 = __float2bfloat16(v0 - __bfloat162float(h0));
                    __nv_bfloat16 l1 = __float2bfloat16(v1 - __bfloat162float(h1));
                    *reinterpret_cast<__nv_bfloat162*>(outH + R * ldc + C) =
                        __halves2bfloat162(h0, h1);
                    *reinterpret_cast<__nv_bfloat162*>(outL + R * ldc + C) =
                        __halves2bfloat162(l0, l1);
                } else {
                    v0 += bias[C];
                    v1 += bias[C + 1];
                    const long long b = R >> 11;
                    const int s = (int)(R & (SS - 1));
                    __nv_bfloat16 h0 = __float2bfloat16(v0);
                    __nv_bfloat16 h1 = __float2bfloat16(v1);
                    __nv_bfloat16 l0 = __float2bfloat16(v0 - __bfloat162float(h0));
                    __nv_bfloat16 l1 = __float2bfloat16(v1 - __bfloat162float(h1));
                    long long a0 = (b * FF + C) * (long long)SS + s;
                    long long a1 = (b * FF + C + 1) * (long long)SS + s;
                    outH[a0] = h0; outL[a0] = l0;
                    outH[a1] = h1; outL[a1] = l1;
                }
            }
        }
    }
}

// ---------------------------------------------------------------------------
// Row softmax (fp32 in) -> hi/lo bf16 out. One CTA per row of 2048.
// ---------------------------------------------------------------------------
__global__ __launch_bounds__(256) void softmax_split_kernel(
    const float* __restrict__ attn,
    __nv_bfloat16* __restrict__ oh, __nv_bfloat16* __restrict__ ol)
{
    __shared__ float red[8];
    const long long row = blockIdx.x;
    const float* p = attn + row * (long long)SS;
    const int tid = threadIdx.x;

    float vals[8];
    float lmax = -1e30f;
#pragma unroll
    for (int i = 0; i < 8; i++) {
        vals[i] = p[tid + i * 256];
        lmax = fmaxf(lmax, vals[i]);
    }
#pragma unroll
    for (int o = 16; o > 0; o >>= 1)
        lmax = fmaxf(lmax, __shfl_xor_sync(0xffffffffu, lmax, o));
    if ((tid & 31) == 0) red[tid >> 5] = lmax;
    __syncthreads();
    float bmax = red[0];
#pragma unroll
    for (int w = 1; w < 8; w++) bmax = fmaxf(bmax, red[w]);
    __syncthreads();

    float lsum = 0.f;
#pragma unroll
    for (int i = 0; i < 8; i++) {
        vals[i] = __expf(vals[i] - bmax);
        lsum += vals[i];
    }
#pragma unroll
    for (int o = 16; o > 0; o >>= 1)
        lsum += __shfl_xor_sync(0xffffffffu, lsum, o);
    if ((tid & 31) == 0) red[tid >> 5] = lsum;
    __syncthreads();
    float total = 0.f;
#pragma unroll
    for (int w = 0; w < 8; w++) total += red[w];
    float inv = 1.0f / total;

#pragma unroll
    for (int i = 0; i < 8; i++) {
        float w = vals[i] * inv;
        __nv_bfloat16 h = __float2bfloat16(w);
        __nv_bfloat16 l = __float2bfloat16(w - __bfloat162float(h));
        oh[row * (long long)SS + tid + i * 256] = h;
        ol[row * (long long)SS + tid + i * 256] = l;
    }
}

// ---------------------------------------------------------------------------
// Launch
// ---------------------------------------------------------------------------
extern "C" void kernel_launch(void* const* d_in, const int* in_sizes, int n_in,
                              void* d_out, int out_size)
{
    (void)in_sizes; (void)n_in; (void)out_size;
    const float* q  = (const float*)d_in[0];
    const float* k  = (const float*)d_in[1];
    const float* v  = (const float*)d_in[2];
    const float* Wq = (const float*)d_in[3];
    const float* bq = (const float*)d_in[4];
    const float* Wk = (const float*)d_in[5];
    const float* bk = (const float*)d_in[6];
    const float* Wv = (const float*)d_in[7];
    const float* bv = (const float*)d_in[8];
    float* out = (float*)d_out;

    __nv_bfloat16 *qh,*ql,*kh,*kl,*vh,*vl, *wqh,*wql,*wkh,*wkl,*wvh,*wvl;
    __nv_bfloat16 *qph,*qpl,*kph,*kpl,*vpth,*vptl, *ath,*atl;
    float *attn;
    cudaGetSymbolAddress((void**)&qh,  g_qh);   cudaGetSymbolAddress((void**)&ql,  g_ql);
    cudaGetSymbolAddress((void**)&kh,  g_kh);   cudaGetSymbolAddress((void**)&kl,  g_kl);
    cudaGetSymbolAddress((void**)&vh,  g_vh);   cudaGetSymbolAddress((void**)&vl,  g_vl);
    cudaGetSymbolAddress((void**)&wqh, g_wqh);  cudaGetSymbolAddress((void**)&wql, g_wql);
    cudaGetSymbolAddress((void**)&wkh, g_wkh);  cudaGetSymbolAddress((void**)&wkl, g_wkl);
    cudaGetSymbolAddress((void**)&wvh, g_wvh);  cudaGetSymbolAddress((void**)&wvl, g_wvl);
    cudaGetSymbolAddress((void**)&qph, g_qph);  cudaGetSymbolAddress((void**)&qpl, g_qpl);
    cudaGetSymbolAddress((void**)&kph, g_kph);  cudaGetSymbolAddress((void**)&kpl, g_kpl);
    cudaGetSymbolAddress((void**)&vpth, g_vpth); cudaGetSymbolAddress((void**)&vptl, g_vptl);
    cudaGetSymbolAddress((void**)&attn, g_attn);
    cudaGetSymbolAddress((void**)&ath, g_ath);  cudaGetSymbolAddress((void**)&atl, g_atl);

    cudaFuncSetAttribute(gemm_mma_kernel,
                         cudaFuncAttributeMaxDynamicSharedMemorySize, SMEMB);

    // 1) split inputs
    const int nQ4 = BS * FF / 4;
    const int nW4 = FF * FF / 4;
    split_kernel<<<nQ4 / 256, 256>>>(q, qh, ql, nQ4);
    split_kernel<<<nQ4 / 256, 256>>>(k, kh, kl, nQ4);
    split_kernel<<<nQ4 / 256, 256>>>(v, vh, vl, nQ4);
    split_kernel<<<nW4 / 256, 256>>>(Wq, wqh, wql, nW4);
    split_kernel<<<nW4 / 256, 256>>>(Wk, wkh, wkl, nW4);
    split_kernel<<<nW4 / 256, 256>>>(Wv, wvh, wvl, nW4);

    dim3 blk(256);

    // 2) projections: [BS,FF] = [BS,FF] @ [FF,FF]^T + bias
    dim3 gproj(FF / 128, BS / 128, 1);
    gemm_mma_kernel<<<gproj, blk, SMEMB>>>(
        qh, ql, wqh, wql, FF, 0, 0, bq, nullptr, 0,
        nullptr, 0, FF, qph, qpl, 1);
    gemm_mma_kernel<<<gproj, blk, SMEMB>>>(
        kh, kl, wkh, wkl, FF, 0, 0, bk, nullptr, 0,
        nullptr, 0, FF, kph, kpl, 1);
    gemm_mma_kernel<<<gproj, blk, SMEMB>>>(
        vh, vl, wvh, wvl, FF, 0, 0, bv, nullptr, 0,
        nullptr, 0, FF, vpth, vptl, 2);

    // 3) logits: per batch [SS,SS] = qp @ kp^T (fp32 out)
    dim3 glog(SS / 128, SS / 128, BB);
    gemm_mma_kernel<<<glog, blk, SMEMB>>>(
        qph, qpl, kph, kpl, FF, (long long)SS * FF, (long long)SS * FF,
        nullptr, nullptr, 0,
        attn, (long long)SS * SS, SS, nullptr, nullptr, 0);

    // 4) softmax + split
    softmax_split_kernel<<<BS, 256>>>(attn, ath, atl);

    // 5) out: per batch [SS,FF] = attn @ vpT^T + q
    dim3 gout(FF / 128, SS / 128, BB);
    gemm_mma_kernel<<<gout, blk, SMEMB>>>(
        ath, atl, vpth, vptl, SS, (long long)SS * SS, (long long)FF * SS,
        nullptr, q, (long long)SS * FF,
        out, (long long)SS * FF, FF, nullptr, nullptr, 0);
}